// round 15
// baseline (speedup 1.0000x reference)
#include <cuda_runtime.h>
#include <cuda_fp16.h>
#include <cstdint>

#define M_TOTAL 32768
#define DHALF   256
#define D2      512
#define KCB     4096

#define BLK_M 128
#define BLK_N 128
#define NCELLS 8192                 // 256 m-tiles x 32 n-tiles
#define KST   16                    // k32-stages per cell
#define MARGIN 1.25f                // > 2x hard screening error bound

// smem: per tile 128 rows x 80B (32 fp16 = 64B data + 16B pad)
#define ROW_BYTES   80
#define TILE_BYTES  (128 * ROW_BYTES)   // 10240
#define STAGE_BYTES (2 * TILE_BYTES)    // A, B = 20480
#define SMEM_TOTAL  (3 * STAGE_BYTES)   // 3-deep ring = 61440

#define OUT_REAL_OFF 0
#define OUT_IMAG_OFF 8388608
#define OUT_LOSS_OFF 16777216
#define OUT_IDX_OFF  16777217

__device__ __align__(16) float g_cnorm[KCB];
__device__ int   g_prev[M_TOTAL];
__device__ int   g_idx[M_TOTAL];
__device__ float g_rowsum[M_TOTAL];
__device__ int   g_work;                         // work-steal counter
// fp16-rounded inputs (K-major) and screened scores
__device__ __align__(16) __half g_zh[(size_t)M_TOTAL * D2];
__device__ __align__(16) __half g_ch[(size_t)KCB * D2];
__device__ __align__(16) __half g_scores[(size_t)M_TOTAL * KCB];

// ---------------------------------------------------------------------------
__device__ __forceinline__ uint32_t smem_u32(const void* p) {
    uint32_t a;
    asm("{ .reg .u64 t; cvta.to.shared.u64 t, %1; cvt.u32.u64 %0, t; }"
        : "=r"(a) : "l"(p));
    return a;
}

__device__ __forceinline__ void cp16(uint32_t dst, const void* src) {
    asm volatile("cp.async.cg.shared.global [%0], [%1], 16;"
                 :: "r"(dst), "l"(src) : "memory");
}
#define CP_COMMIT() asm volatile("cp.async.commit_group;" ::: "memory")
#define CP_WAIT1()  asm volatile("cp.async.wait_group 1;" ::: "memory")

__device__ __forceinline__ void ldmatrix_x4(uint32_t* r, uint32_t addr) {
    asm volatile("ldmatrix.sync.aligned.m8n8.x4.shared.b16 {%0,%1,%2,%3}, [%4];"
                 : "=r"(r[0]), "=r"(r[1]), "=r"(r[2]), "=r"(r[3]) : "r"(addr));
}

__device__ __forceinline__ void mma_f16(float* d, const uint32_t* a,
                                        const uint32_t* b) {
    asm volatile(
        "mma.sync.aligned.m16n8k16.row.col.f32.f16.f16.f32 "
        "{%0,%1,%2,%3},{%4,%5,%6,%7},{%8,%9},{%0,%1,%2,%3};"
        : "+f"(d[0]), "+f"(d[1]), "+f"(d[2]), "+f"(d[3])
        : "r"(a[0]), "r"(a[1]), "r"(a[2]), "r"(a[3]), "r"(b[0]), "r"(b[1]));
}

__device__ __forceinline__ float sig08(float x) {
    float x2 = x * x;
    // 0.8*sigmoid(x) = 0.4 + 0.8*x*p(x^2), odd Taylor to x^9 (|x| <= 1)
    float p = 2.1356922e-05f;
    p = fmaf(p, x2, -2.1081349e-04f);
    p = fmaf(p, x2,  2.0833334e-03f);
    p = fmaf(p, x2, -2.0833333e-02f);
    p = fmaf(p, x2,  0.25f);
    float s = fmaf(0.8f * x, p, 0.4f);
    if (fabsf(x) > 1.0f) s = 0.8f / (1.0f + __expf(-x));
    return s;
}

__device__ __forceinline__ unsigned long long score_key(float s, int n) {
    unsigned u = __float_as_uint(s);
    u = (u & 0x80000000u) ? ~u : (u | 0x80000000u);   // order-preserving
    return ((unsigned long long)u << 32) | (unsigned)n;
}

// ---------------------------------------------------------------------------
// Kernel 0: normalize prev_symbol_idx; reset work counter
// ---------------------------------------------------------------------------
__global__ void prev_kernel(const void* __restrict__ p) {
    const long long* p64 = (const long long*)p;
    const int*       p32 = (const int*)p;
    bool is64 = true;
    for (int t = 0; t < 64; t++) {
        long long v = p64[t];
        if (v < 0 || v >= KCB) { is64 = false; break; }
    }
    int i = blockIdx.x * blockDim.x + threadIdx.x;
    if (i < M_TOTAL) g_prev[i] = is64 ? (int)p64[i] : p32[i];
    if (i == 0) g_work = 0;
}

// ---------------------------------------------------------------------------
// Kernel 1: cnorm[k] = ||codebook[k]||^2 (exact, f32)
// ---------------------------------------------------------------------------
__global__ void cnorm_kernel(const float* __restrict__ cb) {
    int warp = (blockIdx.x * blockDim.x + threadIdx.x) >> 5;
    int lane = threadIdx.x & 31;
    if (warp >= KCB) return;
    const float4* row = reinterpret_cast<const float4*>(cb + (size_t)warp * D2);
    float s = 0.f;
#pragma unroll
    for (int w = 0; w < 4; w++) {
        float4 v = row[lane + 32 * w];
        s += v.x * v.x + v.y * v.y + v.z * v.z + v.w * v.w;
    }
#pragma unroll
    for (int o = 16; o; o >>= 1) s += __shfl_xor_sync(0xffffffffu, s, o);
    if (lane == 0) g_cnorm[warp] = s;
}

// ---------------------------------------------------------------------------
// Kernel 2: f32 -> fp16 (single rounding) for z and codebook
// ---------------------------------------------------------------------------
__global__ void split_kernel(const float* __restrict__ zr,
                             const float* __restrict__ zi,
                             const float* __restrict__ cb) {
    const int zblocks = (M_TOTAL * D2 / 4) / 256;   // 16384
    float4 v;
    __half* d0;
    if (blockIdx.x < zblocks) {
        int g  = blockIdx.x * 256 + threadIdx.x;
        int m  = g >> 7;
        int k4 = (g & 127) * 4;
        v = (k4 < DHALF)
            ? *reinterpret_cast<const float4*>(zr + (size_t)m * DHALF + k4)
            : *reinterpret_cast<const float4*>(zi + (size_t)m * DHALF + (k4 - DHALF));
        d0 = &g_zh[(size_t)m * D2 + k4];
    } else {
        int g = (blockIdx.x - zblocks) * 256 + threadIdx.x;
        v = *reinterpret_cast<const float4*>(cb + (size_t)g * 4);
        d0 = &g_ch[(size_t)g * 4];
    }
    ushort4 o;
    o.x = __half_as_ushort(__float2half_rn(v.x));
    o.y = __half_as_ushort(__float2half_rn(v.y));
    o.z = __half_as_ushort(__float2half_rn(v.z));
    o.w = __half_as_ushort(__float2half_rn(v.w));
    *reinterpret_cast<ushort4*>(d0) = o;
}

// ---------------------------------------------------------------------------
// cp.async one k32-stage (A,B tiles, 128 rows x 64B each); 4 x 16B per thread
// thread covers (row = tid>>1, 32B half = tid&1)
// ---------------------------------------------------------------------------
__device__ __forceinline__ void stage_cp(uint32_t sbase, int slot, int am0,
                                         int bn0, int kb, int tid) {
    const int row = tid >> 1, h = tid & 1;
    const uint32_t d = sbase + slot * STAGE_BYTES + row * ROW_BYTES + h * 32;
    const size_t aoff = (size_t)(am0 + row) * D2 + kb + h * 16;
    const size_t boff = (size_t)(bn0 + row) * D2 + kb + h * 16;
    cp16(d,                   &g_zh[aoff]);
    cp16(d + 16,              &g_zh[aoff + 8]);
    cp16(d + TILE_BYTES,      &g_ch[boff]);
    cp16(d + TILE_BYTES + 16, &g_ch[boff + 8]);
}

// ---------------------------------------------------------------------------
// Kernel 3: persistent work-stolen fp16 SCREENING GEMM (1 term) + bias;
// k32 stages (2 k16 substeps per barrier), 3-deep ring, wait_group 1.
// Stores fp16 scores to g_scores.
// ---------------------------------------------------------------------------
__global__ __launch_bounds__(256, 2) void vq_screen_kernel(const float* __restrict__ adj)
{
    extern __shared__ __align__(16) char smem[];
    __shared__ int sCell[2];
    const uint32_t sbase = smem_u32(smem);

    const int tid    = threadIdx.x;
    const int lane   = tid & 31;
    const int wid    = tid >> 5;
    const int warp_m = wid & 1;       // 0..1  (64 rows)
    const int warp_n = wid >> 1;      // 0..3  (32 cols)

    if (tid == 0) sCell[0] = atomicAdd(&g_work, 1);
    __syncthreads();
    int cur = sCell[0];
    int rs  = 0;                      // ring slot of stage being computed

    if (cur < NCELLS) {
        const int am0 = (cur >> 5) * BLK_M, bn0 = (cur & 31) * BLK_N;
        stage_cp(sbase, 0, am0, bn0, 0,  tid); CP_COMMIT();
        stage_cp(sbase, 1, am0, bn0, 32, tid); CP_COMMIT();
    }

    float acc[4][4][4];
#pragma unroll
    for (int mi = 0; mi < 4; mi++)
#pragma unroll
        for (int ni = 0; ni < 4; ni++)
#pragma unroll
            for (int e = 0; e < 4; e++) acc[mi][ni][e] = 0.f;

    const int arow8 = ((lane >> 3) & 1) * 8 + (lane & 7);    // A row-in-16
    const int akoff = (lane >> 4) * 16;                      // A k-half
    const int bq = lane >> 3, br = lane & 7;
    const int boffs = ((bq >> 1) * 8 + br) * ROW_BYTES + (bq & 1) * 16;

    while (cur < NCELLS) {
        const int am0 = (cur >> 5) * BLK_M;
        const int n0  = (cur & 31) * BLK_N;

        for (int s = 0; s < KST; s++) {
            CP_WAIT1();
            __syncthreads();
            if (s == 10 && tid == 0) sCell[1] = atomicAdd(&g_work, 1);
            if (s < KST - 2) {
                stage_cp(sbase, (rs + 2) % 3, am0, n0, (s + 2) * 32, tid);
            } else {
                const int nx = sCell[1];   // written s==10, barriers since
                if (nx < NCELLS)
                    stage_cp(sbase, (rs + 2) % 3, (nx >> 5) * BLK_M,
                             (nx & 31) * BLK_N, (s - (KST - 2)) * 32, tid);
            }
            CP_COMMIT();

            const uint32_t buf = sbase + rs * STAGE_BYTES;

#pragma unroll
            for (int ks = 0; ks < 2; ks++) {
                const uint32_t kso = ks * 32;
                // B fragments (2 x ldmatrix.x4)
                uint32_t bF[4][2];
                {
                    const uint32_t bb = buf + TILE_BYTES
                                      + (warp_n * 32) * ROW_BYTES + boffs + kso;
                    uint32_t r0[4], r1[4];
                    ldmatrix_x4(r0, bb);
                    ldmatrix_x4(r1, bb + 16 * ROW_BYTES);
                    bF[0][0] = r0[0]; bF[0][1] = r0[1];
                    bF[1][0] = r0[2]; bF[1][1] = r0[3];
                    bF[2][0] = r1[0]; bF[2][1] = r1[1];
                    bF[3][0] = r1[2]; bF[3][1] = r1[3];
                }
                // A fragments
                uint32_t aF[4][4];
#pragma unroll
                for (int mi = 0; mi < 4; mi++)
                    ldmatrix_x4(aF[mi], buf
                        + (warp_m * 64 + mi * 16 + arow8) * ROW_BYTES
                        + akoff + kso);
                // 16 independent MMAs
#pragma unroll
                for (int mi = 0; mi < 4; mi++)
#pragma unroll
                    for (int ni = 0; ni < 4; ni++)
                        mma_f16(acc[mi][ni], aF[mi], bF[ni]);
            }

            // epilogue at end of cell: compute + store fp16 scores
            if (s == KST - 1) {
#pragma unroll
                for (int mi = 0; mi < 4; mi++) {
#pragma unroll
                    for (int h = 0; h < 2; h++) {
                        const int r = warp_m * 64 + mi * 16 + (lane >> 2) + h * 8;
                        const float* arow = adj + (size_t)g_prev[am0 + r] * KCB;
                        __half* srow = &g_scores[(size_t)(am0 + r) * KCB];
#pragma unroll
                        for (int ni = 0; ni < 4; ni++) {
                            const int n = n0 + warp_n * 32 + ni * 8 + (lane & 3) * 2;
                            float2 g  = *reinterpret_cast<const float2*>(arow + n);
                            float2 cn = *reinterpret_cast<const float2*>(g_cnorm + n);
                            float s0 = cn.x - 2.0f * acc[mi][ni][h * 2 + 0] - sig08(g.x);
                            float s1 = cn.y - 2.0f * acc[mi][ni][h * 2 + 1] - sig08(g.y);
                            *reinterpret_cast<__half2*>(srow + n) =
                                __floats2half2_rn(s0, s1);
                        }
                    }
                }
#pragma unroll
                for (int mi = 0; mi < 4; mi++)
#pragma unroll
                    for (int ni = 0; ni < 4; ni++)
#pragma unroll
                        for (int e = 0; e < 4; e++) acc[mi][ni][e] = 0.f;
            }
            rs = (rs == 2) ? 0 : rs + 1;
        }
        cur = sCell[1];
    }
}

// ---------------------------------------------------------------------------
// Kernel 4: per-row filter + exact fp32 rescore -> g_idx
// One 128-thread block per row.
// ---------------------------------------------------------------------------
__global__ __launch_bounds__(128) void filter_kernel(
    const float* __restrict__ zr, const float* __restrict__ zi,
    const float* __restrict__ cb, const float* __restrict__ adj)
{
    __shared__ float zsh[D2];
    __shared__ int   cand[1024];
    __shared__ int   ccount;
    __shared__ float red[4];
    __shared__ float rowmin_sh;

    const int row  = blockIdx.x;
    const int tid  = threadIdx.x;
    const int lane = tid & 31;
    const int wrp  = tid >> 5;

    // load z row (f32 exact)
    {
        int j = tid * 4;
        float4 v = (j < DHALF)
            ? *reinterpret_cast<const float4*>(zr + (size_t)row * DHALF + j)
            : *reinterpret_cast<const float4*>(zi + (size_t)row * DHALF + (j - DHALF));
        *reinterpret_cast<float4*>(&zsh[j]) = v;
    }
    if (tid == 0) ccount = 0;

    // load this thread's 32 scores (64B contiguous)
    const __half* srow = &g_scores[(size_t)row * KCB];
    uint4 raw[4];
#pragma unroll
    for (int i = 0; i < 4; i++)
        raw[i] = *reinterpret_cast<const uint4*>(srow + tid * 32 + i * 8);
    const __half2* h2 = reinterpret_cast<const __half2*>(raw);

    float smin = 1e30f;
#pragma unroll
    for (int i = 0; i < 16; i++) {
        float2 f = __half22float2(h2[i]);
        smin = fminf(smin, fminf(f.x, f.y));
    }
#pragma unroll
    for (int o = 16; o; o >>= 1)
        smin = fminf(smin, __shfl_xor_sync(0xffffffffu, smin, o));
    if (lane == 0) red[wrp] = smin;
    __syncthreads();
    if (tid == 0)
        rowmin_sh = fminf(fminf(red[0], red[1]), fminf(red[2], red[3]));
    __syncthreads();

    const float thr = rowmin_sh + MARGIN;
#pragma unroll
    for (int i = 0; i < 16; i++) {
        float2 f = __half22float2(h2[i]);
        if (f.x <= thr) { int p = atomicAdd(&ccount, 1); if (p < 1024) cand[p] = tid * 32 + i * 2; }
        if (f.y <= thr) { int p = atomicAdd(&ccount, 1); if (p < 1024) cand[p] = tid * 32 + i * 2 + 1; }
    }
    __syncthreads();

    const int cnt = (ccount < 1024) ? ccount : 1024;
    unsigned long long best = ~0ULL;
    const int myprev = g_prev[row];

    for (int i = 0; i < cnt; i++) {
        const int n = cand[i];
        float4 cv = reinterpret_cast<const float4*>(cb + (size_t)n * D2)[tid];
        const int j = tid * 4;
        float d = zsh[j] * cv.x + zsh[j + 1] * cv.y
                + zsh[j + 2] * cv.z + zsh[j + 3] * cv.w;
#pragma unroll
        for (int o = 16; o; o >>= 1) d += __shfl_xor_sync(0xffffffffu, d, o);
        if (lane == 0) red[wrp] = d;
        __syncthreads();
        if (tid == 0) {
            float dot = red[0] + red[1] + red[2] + red[3];
            float s = g_cnorm[n] - 2.0f * dot
                    - sig08(adj[(size_t)myprev * KCB + n]);
            unsigned long long k = score_key(s, n);
            best = (k < best) ? k : best;
        }
        __syncthreads();
    }
    if (tid == 0) g_idx[row] = (int)(best & 0xffffffffu);
}

// ---------------------------------------------------------------------------
// Kernel 5: gather z_q = codebook[idx], write outputs, per-row squared error
// ---------------------------------------------------------------------------
__global__ void gather_kernel(const float* __restrict__ zr,
                              const float* __restrict__ zi,
                              const float* __restrict__ cb,
                              float* __restrict__ out)
{
    __shared__ float sw[4];
    const int row = blockIdx.x;
    const int tid = threadIdx.x;
    const int idx = g_idx[row];
    const int j   = tid * 4;

    float4 c = *reinterpret_cast<const float4*>(cb + (size_t)idx * D2 + j);
    float4 z;
    float* o;
    if (j < DHALF) {
        z = *reinterpret_cast<const float4*>(zr + (size_t)row * DHALF + j);
        o = out + OUT_REAL_OFF + (size_t)row * DHALF + j;
    } else {
        z = *reinterpret_cast<const float4*>(zi + (size_t)row * DHALF + (j - DHALF));
        o = out + OUT_IMAG_OFF + (size_t)row * DHALF + (j - DHALF);
    }
    *reinterpret_cast<float4*>(o) = c;

    float dx = c.x - z.x, dy = c.y - z.y, dz = c.z - z.z, dw = c.w - z.w;
    float s = dx * dx + dy * dy + dz * dz + dw * dw;
#pragma unroll
    for (int of = 16; of; of >>= 1) s += __shfl_xor_sync(0xffffffffu, s, of);
    if ((tid & 31) == 0) sw[tid >> 5] = s;
    __syncthreads();
    if (tid == 0) {
        g_rowsum[row] = sw[0] + sw[1] + sw[2] + sw[3];
        out[OUT_IDX_OFF + row] = (float)idx;
    }
}

// ---------------------------------------------------------------------------
// Kernel 6: deterministic final loss reduction
// ---------------------------------------------------------------------------
__global__ void loss_kernel(float* __restrict__ out) {
    __shared__ float sm[1024];
    const int tid = threadIdx.x;
    float s = 0.f;
#pragma unroll 1
    for (int k = 0; k < 32; k++) s += g_rowsum[tid + 1024 * k];
    sm[tid] = s;
    __syncthreads();
    for (int off = 512; off; off >>= 1) {
        if (tid < off) sm[tid] += sm[tid + off];
        __syncthreads();
    }
    if (tid == 0) out[OUT_LOSS_OFF] = sm[0] * (1.01f / 16777216.0f);
}

// ---------------------------------------------------------------------------
extern "C" void kernel_launch(void* const* d_in, const int* in_sizes, int n_in,
                              void* d_out, int out_size) {
    const float* zr   = (const float*)d_in[0];
    const float* zi   = (const float*)d_in[1];
    const void*  prev = d_in[2];
    const float* cb   = (const float*)d_in[3];
    const float* adj  = (const float*)d_in[4];
    float* out = (float*)d_out;

    cudaFuncSetAttribute(vq_screen_kernel,
                         cudaFuncAttributeMaxDynamicSharedMemorySize, SMEM_TOTAL);

    int dev = 0, nsm = 148;
    cudaGetDevice(&dev);
    cudaDeviceGetAttribute(&nsm, cudaDevAttrMultiProcessorCount, dev);
    int grid = 2 * nsm;
    if (grid > NCELLS) grid = NCELLS;

    prev_kernel<<<(M_TOTAL + 255) / 256, 256>>>(prev);
    cnorm_kernel<<<KCB / 8, 256>>>(cb);
    split_kernel<<<(M_TOTAL * D2 / 4) / 256 + (KCB * D2 / 4) / 256, 256>>>(zr, zi, cb);
    vq_screen_kernel<<<grid, 256, SMEM_TOTAL>>>(adj);   // launch #4 -> ncu
    filter_kernel<<<M_TOTAL, 128>>>(zr, zi, cb, adj);
    gather_kernel<<<M_TOTAL, 128>>>(zr, zi, cb, out);
    loss_kernel<<<1, 1024>>>(out);
}

// round 16
// speedup vs baseline: 1.0779x; 1.0779x over previous
#include <cuda_runtime.h>
#include <cuda_fp16.h>
#include <cstdint>

#define M_TOTAL 32768
#define DHALF   256
#define D2      512
#define KCB     4096

#define BLK_M 128
#define BLK_N 64
#define NCELLS 16384                // 256 m-tiles x 64 n-tiles
#define KST   16                    // k32-stages per cell
#define MARGIN 1.25f                // > 2x hard screening error bound

// smem: rows of 80B (64B data + 16B pad)
#define ROW_BYTES   80
#define A_TILE_BYTES (128 * ROW_BYTES)          // 10240
#define B_TILE_BYTES (64 * ROW_BYTES)           // 5120
#define STAGE_BYTES  (A_TILE_BYTES + B_TILE_BYTES)  // 15360
#define SMEM_TOTAL   (3 * STAGE_BYTES)          // 3-deep ring = 46080

#define OUT_REAL_OFF 0
#define OUT_IMAG_OFF 8388608
#define OUT_LOSS_OFF 16777216
#define OUT_IDX_OFF  16777217

__device__ __align__(16) float g_cnorm[KCB];
__device__ int   g_prev[M_TOTAL];
__device__ int   g_idx[M_TOTAL];
__device__ float g_rowsum[M_TOTAL];
__device__ int   g_work;                         // work-steal counter
// fp16-rounded inputs (K-major) and screened scores
__device__ __align__(16) __half g_zh[(size_t)M_TOTAL * D2];
__device__ __align__(16) __half g_ch[(size_t)KCB * D2];
__device__ __align__(16) __half g_scores[(size_t)M_TOTAL * KCB];

// ---------------------------------------------------------------------------
__device__ __forceinline__ uint32_t smem_u32(const void* p) {
    uint32_t a;
    asm("{ .reg .u64 t; cvta.to.shared.u64 t, %1; cvt.u32.u64 %0, t; }"
        : "=r"(a) : "l"(p));
    return a;
}

__device__ __forceinline__ void cp16(uint32_t dst, const void* src) {
    asm volatile("cp.async.cg.shared.global [%0], [%1], 16;"
                 :: "r"(dst), "l"(src) : "memory");
}
#define CP_COMMIT() asm volatile("cp.async.commit_group;" ::: "memory")
#define CP_WAIT1()  asm volatile("cp.async.wait_group 1;" ::: "memory")

__device__ __forceinline__ void ldmatrix_x4(uint32_t* r, uint32_t addr) {
    asm volatile("ldmatrix.sync.aligned.m8n8.x4.shared.b16 {%0,%1,%2,%3}, [%4];"
                 : "=r"(r[0]), "=r"(r[1]), "=r"(r[2]), "=r"(r[3]) : "r"(addr));
}

__device__ __forceinline__ void mma_f16(float* d, const uint32_t* a,
                                        const uint32_t* b) {
    asm volatile(
        "mma.sync.aligned.m16n8k16.row.col.f32.f16.f16.f32 "
        "{%0,%1,%2,%3},{%4,%5,%6,%7},{%8,%9},{%0,%1,%2,%3};"
        : "+f"(d[0]), "+f"(d[1]), "+f"(d[2]), "+f"(d[3])
        : "r"(a[0]), "r"(a[1]), "r"(a[2]), "r"(a[3]), "r"(b[0]), "r"(b[1]));
}

__device__ __forceinline__ float sig08(float x) {
    float x2 = x * x;
    // 0.8*sigmoid(x) = 0.4 + 0.8*x*p(x^2), odd Taylor to x^9 (|x| <= 1)
    float p = 2.1356922e-05f;
    p = fmaf(p, x2, -2.1081349e-04f);
    p = fmaf(p, x2,  2.0833334e-03f);
    p = fmaf(p, x2, -2.0833333e-02f);
    p = fmaf(p, x2,  0.25f);
    float s = fmaf(0.8f * x, p, 0.4f);
    if (fabsf(x) > 1.0f) s = 0.8f / (1.0f + __expf(-x));
    return s;
}

__device__ __forceinline__ unsigned long long score_key(float s, int n) {
    unsigned u = __float_as_uint(s);
    u = (u & 0x80000000u) ? ~u : (u | 0x80000000u);   // order-preserving
    return ((unsigned long long)u << 32) | (unsigned)n;
}

// ---------------------------------------------------------------------------
// Kernel 0: normalize prev_symbol_idx; reset work counter
// ---------------------------------------------------------------------------
__global__ void prev_kernel(const void* __restrict__ p) {
    const long long* p64 = (const long long*)p;
    const int*       p32 = (const int*)p;
    bool is64 = true;
    for (int t = 0; t < 64; t++) {
        long long v = p64[t];
        if (v < 0 || v >= KCB) { is64 = false; break; }
    }
    int i = blockIdx.x * blockDim.x + threadIdx.x;
    if (i < M_TOTAL) g_prev[i] = is64 ? (int)p64[i] : p32[i];
    if (i == 0) g_work = 0;
}

// ---------------------------------------------------------------------------
// Kernel 1: cnorm[k] = ||codebook[k]||^2 (exact, f32)
// ---------------------------------------------------------------------------
__global__ void cnorm_kernel(const float* __restrict__ cb) {
    int warp = (blockIdx.x * blockDim.x + threadIdx.x) >> 5;
    int lane = threadIdx.x & 31;
    if (warp >= KCB) return;
    const float4* row = reinterpret_cast<const float4*>(cb + (size_t)warp * D2);
    float s = 0.f;
#pragma unroll
    for (int w = 0; w < 4; w++) {
        float4 v = row[lane + 32 * w];
        s += v.x * v.x + v.y * v.y + v.z * v.z + v.w * v.w;
    }
#pragma unroll
    for (int o = 16; o; o >>= 1) s += __shfl_xor_sync(0xffffffffu, s, o);
    if (lane == 0) g_cnorm[warp] = s;
}

// ---------------------------------------------------------------------------
// Kernel 2: f32 -> fp16 (single rounding) for z and codebook
// ---------------------------------------------------------------------------
__global__ void split_kernel(const float* __restrict__ zr,
                             const float* __restrict__ zi,
                             const float* __restrict__ cb) {
    const int zblocks = (M_TOTAL * D2 / 4) / 256;   // 16384
    float4 v;
    __half* d0;
    if (blockIdx.x < zblocks) {
        int g  = blockIdx.x * 256 + threadIdx.x;
        int m  = g >> 7;
        int k4 = (g & 127) * 4;
        v = (k4 < DHALF)
            ? *reinterpret_cast<const float4*>(zr + (size_t)m * DHALF + k4)
            : *reinterpret_cast<const float4*>(zi + (size_t)m * DHALF + (k4 - DHALF));
        d0 = &g_zh[(size_t)m * D2 + k4];
    } else {
        int g = (blockIdx.x - zblocks) * 256 + threadIdx.x;
        v = *reinterpret_cast<const float4*>(cb + (size_t)g * 4);
        d0 = &g_ch[(size_t)g * 4];
    }
    ushort4 o;
    o.x = __half_as_ushort(__float2half_rn(v.x));
    o.y = __half_as_ushort(__float2half_rn(v.y));
    o.z = __half_as_ushort(__float2half_rn(v.z));
    o.w = __half_as_ushort(__float2half_rn(v.w));
    *reinterpret_cast<ushort4*>(d0) = o;
}

// ---------------------------------------------------------------------------
// cp.async one k32-stage: A 128 rows x 64B, B 64 rows x 64B.
// A: all 256 threads (row = tid>>1, half = tid&1, 2 cp16).
// B: threads < 128 (row = tid>>1, half = tid&1, 2 cp16).
// ---------------------------------------------------------------------------
__device__ __forceinline__ void stage_cp(uint32_t sbase, int slot, int am0,
                                         int bn0, int kb, int tid) {
    const int row = tid >> 1, h = tid & 1;
    const uint32_t base = sbase + slot * STAGE_BYTES;
    {
        const uint32_t d = base + row * ROW_BYTES + h * 32;
        const size_t aoff = (size_t)(am0 + row) * D2 + kb + h * 16;
        cp16(d,      &g_zh[aoff]);
        cp16(d + 16, &g_zh[aoff + 8]);
    }
    if (tid < 128) {
        const uint32_t d = base + A_TILE_BYTES + row * ROW_BYTES + h * 32;
        const size_t boff = (size_t)(bn0 + row) * D2 + kb + h * 16;
        cp16(d,      &g_ch[boff]);
        cp16(d + 16, &g_ch[boff + 8]);
    }
}

// ---------------------------------------------------------------------------
// Kernel 3: persistent work-stolen fp16 SCREENING GEMM (1 term) + bias.
// Block tile 128x64, 8 warps (4m x 2n), warp tile 32x32, occ 3 (24 warps/SM).
// k32 stages, 3-deep ring, wait_group 1. Stores fp16 scores to g_scores.
// ---------------------------------------------------------------------------
__global__ __launch_bounds__(256, 3) void vq_screen_kernel(const float* __restrict__ adj)
{
    extern __shared__ __align__(16) char smem[];
    __shared__ int sCell[2];
    const uint32_t sbase = smem_u32(smem);

    const int tid    = threadIdx.x;
    const int lane   = tid & 31;
    const int wid    = tid >> 5;
    const int warp_m = wid & 3;       // 0..3  (32 rows)
    const int warp_n = wid >> 2;      // 0..1  (32 cols)

    if (tid == 0) sCell[0] = atomicAdd(&g_work, 1);
    __syncthreads();
    int cur = sCell[0];
    int rs  = 0;                      // ring slot of stage being computed

    if (cur < NCELLS) {
        const int am0 = (cur >> 6) * BLK_M, bn0 = (cur & 63) * BLK_N;
        stage_cp(sbase, 0, am0, bn0, 0,  tid); CP_COMMIT();
        stage_cp(sbase, 1, am0, bn0, 32, tid); CP_COMMIT();
    }

    float acc[2][4][4];
#pragma unroll
    for (int mi = 0; mi < 2; mi++)
#pragma unroll
        for (int ni = 0; ni < 4; ni++)
#pragma unroll
            for (int e = 0; e < 4; e++) acc[mi][ni][e] = 0.f;

    const int arow8 = ((lane >> 3) & 1) * 8 + (lane & 7);    // A row-in-16
    const int akoff = (lane >> 4) * 16;                      // A k-half
    const int bq = lane >> 3, br = lane & 7;
    const int boffs = ((bq >> 1) * 8 + br) * ROW_BYTES + (bq & 1) * 16;

    while (cur < NCELLS) {
        const int am0 = (cur >> 6) * BLK_M;
        const int n0  = (cur & 63) * BLK_N;

        for (int s = 0; s < KST; s++) {
            CP_WAIT1();
            __syncthreads();
            if (s == 10 && tid == 0) sCell[1] = atomicAdd(&g_work, 1);
            if (s < KST - 2) {
                stage_cp(sbase, (rs + 2) % 3, am0, n0, (s + 2) * 32, tid);
            } else {
                const int nx = sCell[1];   // written s==10, barriers since
                if (nx < NCELLS)
                    stage_cp(sbase, (rs + 2) % 3, (nx >> 6) * BLK_M,
                             (nx & 63) * BLK_N, (s - (KST - 2)) * 32, tid);
            }
            CP_COMMIT();

            const uint32_t buf = sbase + rs * STAGE_BYTES;

#pragma unroll
            for (int ks = 0; ks < 2; ks++) {
                const uint32_t kso = ks * 32;
                // B fragments (2 x ldmatrix.x4)
                uint32_t bF[4][2];
                {
                    const uint32_t bb = buf + A_TILE_BYTES
                                      + (warp_n * 32) * ROW_BYTES + boffs + kso;
                    uint32_t r0[4], r1[4];
                    ldmatrix_x4(r0, bb);
                    ldmatrix_x4(r1, bb + 16 * ROW_BYTES);
                    bF[0][0] = r0[0]; bF[0][1] = r0[1];
                    bF[1][0] = r0[2]; bF[1][1] = r0[3];
                    bF[2][0] = r1[0]; bF[2][1] = r1[1];
                    bF[3][0] = r1[2]; bF[3][1] = r1[3];
                }
                // A fragments (2 x ldmatrix.x4)
                uint32_t aF[2][4];
#pragma unroll
                for (int mi = 0; mi < 2; mi++)
                    ldmatrix_x4(aF[mi], buf
                        + (warp_m * 32 + mi * 16 + arow8) * ROW_BYTES
                        + akoff + kso);
                // 8 independent MMAs
#pragma unroll
                for (int mi = 0; mi < 2; mi++)
#pragma unroll
                    for (int ni = 0; ni < 4; ni++)
                        mma_f16(acc[mi][ni], aF[mi], bF[ni]);
            }

            // epilogue at end of cell: compute + store fp16 scores
            if (s == KST - 1) {
#pragma unroll
                for (int mi = 0; mi < 2; mi++) {
#pragma unroll
                    for (int h = 0; h < 2; h++) {
                        const int r = warp_m * 32 + mi * 16 + (lane >> 2) + h * 8;
                        const float* arow = adj + (size_t)g_prev[am0 + r] * KCB;
                        __half* srow = &g_scores[(size_t)(am0 + r) * KCB];
#pragma unroll
                        for (int ni = 0; ni < 4; ni++) {
                            const int n = n0 + warp_n * 32 + ni * 8 + (lane & 3) * 2;
                            float2 g  = *reinterpret_cast<const float2*>(arow + n);
                            float2 cn = *reinterpret_cast<const float2*>(g_cnorm + n);
                            float s0 = cn.x - 2.0f * acc[mi][ni][h * 2 + 0] - sig08(g.x);
                            float s1 = cn.y - 2.0f * acc[mi][ni][h * 2 + 1] - sig08(g.y);
                            *reinterpret_cast<__half2*>(srow + n) =
                                __floats2half2_rn(s0, s1);
                        }
                    }
                }
#pragma unroll
                for (int mi = 0; mi < 2; mi++)
#pragma unroll
                    for (int ni = 0; ni < 4; ni++)
#pragma unroll
                        for (int e = 0; e < 4; e++) acc[mi][ni][e] = 0.f;
            }
            rs = (rs == 2) ? 0 : rs + 1;
        }
        cur = sCell[1];
    }
}

// ---------------------------------------------------------------------------
// Kernel 4: per-row filter + exact fp32 rescore -> g_idx
// One 128-thread block per row.
// ---------------------------------------------------------------------------
__global__ __launch_bounds__(128) void filter_kernel(
    const float* __restrict__ zr, const float* __restrict__ zi,
    const float* __restrict__ cb, const float* __restrict__ adj)
{
    __shared__ float zsh[D2];
    __shared__ int   cand[1024];
    __shared__ int   ccount;
    __shared__ float red[4];
    __shared__ float rowmin_sh;

    const int row  = blockIdx.x;
    const int tid  = threadIdx.x;
    const int lane = tid & 31;
    const int wrp  = tid >> 5;

    // load z row (f32 exact)
    {
        int j = tid * 4;
        float4 v = (j < DHALF)
            ? *reinterpret_cast<const float4*>(zr + (size_t)row * DHALF + j)
            : *reinterpret_cast<const float4*>(zi + (size_t)row * DHALF + (j - DHALF));
        *reinterpret_cast<float4*>(&zsh[j]) = v;
    }
    if (tid == 0) ccount = 0;

    // load this thread's 32 scores (64B contiguous)
    const __half* srow = &g_scores[(size_t)row * KCB];
    uint4 raw[4];
#pragma unroll
    for (int i = 0; i < 4; i++)
        raw[i] = *reinterpret_cast<const uint4*>(srow + tid * 32 + i * 8);
    const __half2* h2 = reinterpret_cast<const __half2*>(raw);

    float smin = 1e30f;
#pragma unroll
    for (int i = 0; i < 16; i++) {
        float2 f = __half22float2(h2[i]);
        smin = fminf(smin, fminf(f.x, f.y));
    }
#pragma unroll
    for (int o = 16; o; o >>= 1)
        smin = fminf(smin, __shfl_xor_sync(0xffffffffu, smin, o));
    if (lane == 0) red[wrp] = smin;
    __syncthreads();
    if (tid == 0)
        rowmin_sh = fminf(fminf(red[0], red[1]), fminf(red[2], red[3]));
    __syncthreads();

    const float thr = rowmin_sh + MARGIN;
#pragma unroll
    for (int i = 0; i < 16; i++) {
        float2 f = __half22float2(h2[i]);
        if (f.x <= thr) { int p = atomicAdd(&ccount, 1); if (p < 1024) cand[p] = tid * 32 + i * 2; }
        if (f.y <= thr) { int p = atomicAdd(&ccount, 1); if (p < 1024) cand[p] = tid * 32 + i * 2 + 1; }
    }
    __syncthreads();

    const int cnt = (ccount < 1024) ? ccount : 1024;
    unsigned long long best = ~0ULL;
    const int myprev = g_prev[row];

    for (int i = 0; i < cnt; i++) {
        const int n = cand[i];
        float4 cv = reinterpret_cast<const float4*>(cb + (size_t)n * D2)[tid];
        const int j = tid * 4;
        float d = zsh[j] * cv.x + zsh[j + 1] * cv.y
                + zsh[j + 2] * cv.z + zsh[j + 3] * cv.w;
#pragma unroll
        for (int o = 16; o; o >>= 1) d += __shfl_xor_sync(0xffffffffu, d, o);
        if (lane == 0) red[wrp] = d;
        __syncthreads();
        if (tid == 0) {
            float dot = red[0] + red[1] + red[2] + red[3];
            float s = g_cnorm[n] - 2.0f * dot
                    - sig08(adj[(size_t)myprev * KCB + n]);
            unsigned long long k = score_key(s, n);
            best = (k < best) ? k : best;
        }
        __syncthreads();
    }
    if (tid == 0) g_idx[row] = (int)(best & 0xffffffffu);
}

// ---------------------------------------------------------------------------
// Kernel 5: gather z_q = codebook[idx], write outputs, per-row squared error
// ---------------------------------------------------------------------------
__global__ void gather_kernel(const float* __restrict__ zr,
                              const float* __restrict__ zi,
                              const float* __restrict__ cb,
                              float* __restrict__ out)
{
    __shared__ float sw[4];
    const int row = blockIdx.x;
    const int tid = threadIdx.x;
    const int idx = g_idx[row];
    const int j   = tid * 4;

    float4 c = *reinterpret_cast<const float4*>(cb + (size_t)idx * D2 + j);
    float4 z;
    float* o;
    if (j < DHALF) {
        z = *reinterpret_cast<const float4*>(zr + (size_t)row * DHALF + j);
        o = out + OUT_REAL_OFF + (size_t)row * DHALF + j;
    } else {
        z = *reinterpret_cast<const float4*>(zi + (size_t)row * DHALF + (j - DHALF));
        o = out + OUT_IMAG_OFF + (size_t)row * DHALF + (j - DHALF);
    }
    *reinterpret_cast<float4*>(o) = c;

    float dx = c.x - z.x, dy = c.y - z.y, dz = c.z - z.z, dw = c.w - z.w;
    float s = dx * dx + dy * dy + dz * dz + dw * dw;
#pragma unroll
    for (int of = 16; of; of >>= 1) s += __shfl_xor_sync(0xffffffffu, s, of);
    if ((tid & 31) == 0) sw[tid >> 5] = s;
    __syncthreads();
    if (tid == 0) {
        g_rowsum[row] = sw[0] + sw[1] + sw[2] + sw[3];
        out[OUT_IDX_OFF + row] = (float)idx;
    }
}

// ---------------------------------------------------------------------------
// Kernel 6: deterministic final loss reduction
// ---------------------------------------------------------------------------
__global__ void loss_kernel(float* __restrict__ out) {
    __shared__ float sm[1024];
    const int tid = threadIdx.x;
    float s = 0.f;
#pragma unroll 1
    for (int k = 0; k < 32; k++) s += g_rowsum[tid + 1024 * k];
    sm[tid] = s;
    __syncthreads();
    for (int off = 512; off; off >>= 1) {
        if (tid < off) sm[tid] += sm[tid + off];
        __syncthreads();
    }
    if (tid == 0) out[OUT_LOSS_OFF] = sm[0] * (1.01f / 16777216.0f);
}

// ---------------------------------------------------------------------------
extern "C" void kernel_launch(void* const* d_in, const int* in_sizes, int n_in,
                              void* d_out, int out_size) {
    const float* zr   = (const float*)d_in[0];
    const float* zi   = (const float*)d_in[1];
    const void*  prev = d_in[2];
    const float* cb   = (const float*)d_in[3];
    const float* adj  = (const float*)d_in[4];
    float* out = (float*)d_out;

    cudaFuncSetAttribute(vq_screen_kernel,
                         cudaFuncAttributeMaxDynamicSharedMemorySize, SMEM_TOTAL);

    int dev = 0, nsm = 148;
    cudaGetDevice(&dev);
    cudaDeviceGetAttribute(&nsm, cudaDevAttrMultiProcessorCount, dev);
    int grid = 3 * nsm;
    if (grid > NCELLS) grid = NCELLS;

    prev_kernel<<<(M_TOTAL + 255) / 256, 256>>>(prev);
    cnorm_kernel<<<KCB / 8, 256>>>(cb);
    split_kernel<<<(M_TOTAL * D2 / 4) / 256 + (KCB * D2 / 4) / 256, 256>>>(zr, zi, cb);
    vq_screen_kernel<<<grid, 256, SMEM_TOTAL>>>(adj);   // launch #4 -> ncu
    filter_kernel<<<M_TOTAL, 128>>>(zr, zi, cb, adj);
    gather_kernel<<<M_TOTAL, 128>>>(zr, zi, cb, out);
    loss_kernel<<<1, 1024>>>(out);
}

// round 17
// speedup vs baseline: 1.2375x; 1.1480x over previous
#include <cuda_runtime.h>
#include <cuda_fp16.h>
#include <cstdint>

#define M_TOTAL 32768
#define DHALF   256
#define D2      512
#define KCB     4096

#define BLK_M 128
#define BLK_N 64
#define NCELLS 16384                // 256 m-tiles x 64 n-tiles
#define KST   16                    // k32-stages per cell
// screen omits the sigmoid bias (range [0,0.8]); margin = 0.8 + 2*fp16 err
#define MARGIN 2.05f

// smem: rows of 80B (64B data + 16B pad)
#define ROW_BYTES   80
#define A_TILE_BYTES (128 * ROW_BYTES)          // 10240
#define B_TILE_BYTES (64 * ROW_BYTES)           // 5120
#define STAGE_BYTES  (A_TILE_BYTES + B_TILE_BYTES)  // 15360
#define SMEM_TOTAL   (3 * STAGE_BYTES)          // 3-deep ring = 46080

#define OUT_REAL_OFF 0
#define OUT_IMAG_OFF 8388608
#define OUT_LOSS_OFF 16777216
#define OUT_IDX_OFF  16777217

__device__ __align__(16) float g_cnorm[KCB];
__device__ int   g_prev[M_TOTAL];
__device__ int   g_idx[M_TOTAL];
__device__ float g_rowsum[M_TOTAL];
__device__ int   g_work;                         // work-steal counter
// fp16-rounded inputs (K-major) and screened scores
__device__ __align__(16) __half g_zh[(size_t)M_TOTAL * D2];
__device__ __align__(16) __half g_ch[(size_t)KCB * D2];
__device__ __align__(16) __half g_scores[(size_t)M_TOTAL * KCB];

// ---------------------------------------------------------------------------
__device__ __forceinline__ uint32_t smem_u32(const void* p) {
    uint32_t a;
    asm("{ .reg .u64 t; cvta.to.shared.u64 t, %1; cvt.u32.u64 %0, t; }"
        : "=r"(a) : "l"(p));
    return a;
}

__device__ __forceinline__ void cp16(uint32_t dst, const void* src) {
    asm volatile("cp.async.cg.shared.global [%0], [%1], 16;"
                 :: "r"(dst), "l"(src) : "memory");
}
#define CP_COMMIT() asm volatile("cp.async.commit_group;" ::: "memory")
#define CP_WAIT1()  asm volatile("cp.async.wait_group 1;" ::: "memory")

__device__ __forceinline__ void ldmatrix_x4(uint32_t* r, uint32_t addr) {
    asm volatile("ldmatrix.sync.aligned.m8n8.x4.shared.b16 {%0,%1,%2,%3}, [%4];"
                 : "=r"(r[0]), "=r"(r[1]), "=r"(r[2]), "=r"(r[3]) : "r"(addr));
}

__device__ __forceinline__ void mma_f16(float* d, const uint32_t* a,
                                        const uint32_t* b) {
    asm volatile(
        "mma.sync.aligned.m16n8k16.row.col.f32.f16.f16.f32 "
        "{%0,%1,%2,%3},{%4,%5,%6,%7},{%8,%9},{%0,%1,%2,%3};"
        : "+f"(d[0]), "+f"(d[1]), "+f"(d[2]), "+f"(d[3])
        : "r"(a[0]), "r"(a[1]), "r"(a[2]), "r"(a[3]), "r"(b[0]), "r"(b[1]));
}

__device__ __forceinline__ float sig08(float x) {
    float x2 = x * x;
    // 0.8*sigmoid(x) = 0.4 + 0.8*x*p(x^2), odd Taylor to x^9 (|x| <= 1)
    float p = 2.1356922e-05f;
    p = fmaf(p, x2, -2.1081349e-04f);
    p = fmaf(p, x2,  2.0833334e-03f);
    p = fmaf(p, x2, -2.0833333e-02f);
    p = fmaf(p, x2,  0.25f);
    float s = fmaf(0.8f * x, p, 0.4f);
    if (fabsf(x) > 1.0f) s = 0.8f / (1.0f + __expf(-x));
    return s;
}

__device__ __forceinline__ unsigned long long score_key(float s, int n) {
    unsigned u = __float_as_uint(s);
    u = (u & 0x80000000u) ? ~u : (u | 0x80000000u);   // order-preserving
    return ((unsigned long long)u << 32) | (unsigned)n;
}

// ---------------------------------------------------------------------------
// Kernel 0: normalize prev_symbol_idx; reset work counter
// ---------------------------------------------------------------------------
__global__ void prev_kernel(const void* __restrict__ p) {
    const long long* p64 = (const long long*)p;
    const int*       p32 = (const int*)p;
    bool is64 = true;
    for (int t = 0; t < 64; t++) {
        long long v = p64[t];
        if (v < 0 || v >= KCB) { is64 = false; break; }
    }
    int i = blockIdx.x * blockDim.x + threadIdx.x;
    if (i < M_TOTAL) g_prev[i] = is64 ? (int)p64[i] : p32[i];
    if (i == 0) g_work = 0;
}

// ---------------------------------------------------------------------------
// Kernel 1: cnorm[k] = ||codebook[k]||^2 (exact, f32)
// ---------------------------------------------------------------------------
__global__ void cnorm_kernel(const float* __restrict__ cb) {
    int warp = (blockIdx.x * blockDim.x + threadIdx.x) >> 5;
    int lane = threadIdx.x & 31;
    if (warp >= KCB) return;
    const float4* row = reinterpret_cast<const float4*>(cb + (size_t)warp * D2);
    float s = 0.f;
#pragma unroll
    for (int w = 0; w < 4; w++) {
        float4 v = row[lane + 32 * w];
        s += v.x * v.x + v.y * v.y + v.z * v.z + v.w * v.w;
    }
#pragma unroll
    for (int o = 16; o; o >>= 1) s += __shfl_xor_sync(0xffffffffu, s, o);
    if (lane == 0) g_cnorm[warp] = s;
}

// ---------------------------------------------------------------------------
// Kernel 2: f32 -> fp16 (single rounding) for z and codebook
// ---------------------------------------------------------------------------
__global__ void split_kernel(const float* __restrict__ zr,
                             const float* __restrict__ zi,
                             const float* __restrict__ cb) {
    const int zblocks = (M_TOTAL * D2 / 4) / 256;   // 16384
    float4 v;
    __half* d0;
    if (blockIdx.x < zblocks) {
        int g  = blockIdx.x * 256 + threadIdx.x;
        int m  = g >> 7;
        int k4 = (g & 127) * 4;
        v = (k4 < DHALF)
            ? *reinterpret_cast<const float4*>(zr + (size_t)m * DHALF + k4)
            : *reinterpret_cast<const float4*>(zi + (size_t)m * DHALF + (k4 - DHALF));
        d0 = &g_zh[(size_t)m * D2 + k4];
    } else {
        int g = (blockIdx.x - zblocks) * 256 + threadIdx.x;
        v = *reinterpret_cast<const float4*>(cb + (size_t)g * 4);
        d0 = &g_ch[(size_t)g * 4];
    }
    ushort4 o;
    o.x = __half_as_ushort(__float2half_rn(v.x));
    o.y = __half_as_ushort(__float2half_rn(v.y));
    o.z = __half_as_ushort(__float2half_rn(v.z));
    o.w = __half_as_ushort(__float2half_rn(v.w));
    *reinterpret_cast<ushort4*>(d0) = o;
}

// ---------------------------------------------------------------------------
// cp.async one k32-stage: A 128 rows x 64B, B 64 rows x 64B.
// ---------------------------------------------------------------------------
__device__ __forceinline__ void stage_cp(uint32_t sbase, int slot, int am0,
                                         int bn0, int kb, int tid) {
    const int row = tid >> 1, h = tid & 1;
    const uint32_t base = sbase + slot * STAGE_BYTES;
    {
        const uint32_t d = base + row * ROW_BYTES + h * 32;
        const size_t aoff = (size_t)(am0 + row) * D2 + kb + h * 16;
        cp16(d,      &g_zh[aoff]);
        cp16(d + 16, &g_zh[aoff + 8]);
    }
    if (tid < 128) {
        const uint32_t d = base + A_TILE_BYTES + row * ROW_BYTES + h * 32;
        const size_t boff = (size_t)(bn0 + row) * D2 + kb + h * 16;
        cp16(d,      &g_ch[boff]);
        cp16(d + 16, &g_ch[boff + 8]);
    }
}

// ---------------------------------------------------------------------------
// Kernel 3: persistent work-stolen fp16 SCREENING GEMM + cnorm (no bias).
// Block tile 128x64, 8 warps (4m x 2n), warp tile 32x32, occ 4 (32 warps/SM).
// ---------------------------------------------------------------------------
__global__ __launch_bounds__(256, 4) void vq_screen_kernel()
{
    extern __shared__ __align__(16) char smem[];
    __shared__ int sCell[2];
    const uint32_t sbase = smem_u32(smem);

    const int tid    = threadIdx.x;
    const int lane   = tid & 31;
    const int wid    = tid >> 5;
    const int warp_m = wid & 3;       // 0..3  (32 rows)
    const int warp_n = wid >> 2;      // 0..1  (32 cols)

    if (tid == 0) sCell[0] = atomicAdd(&g_work, 1);
    __syncthreads();
    int cur = sCell[0];
    int rs  = 0;                      // ring slot of stage being computed

    if (cur < NCELLS) {
        const int am0 = (cur >> 6) * BLK_M, bn0 = (cur & 63) * BLK_N;
        stage_cp(sbase, 0, am0, bn0, 0,  tid); CP_COMMIT();
        stage_cp(sbase, 1, am0, bn0, 32, tid); CP_COMMIT();
    }

    float acc[2][4][4];
#pragma unroll
    for (int mi = 0; mi < 2; mi++)
#pragma unroll
        for (int ni = 0; ni < 4; ni++)
#pragma unroll
            for (int e = 0; e < 4; e++) acc[mi][ni][e] = 0.f;

    const int arow8 = ((lane >> 3) & 1) * 8 + (lane & 7);    // A row-in-16
    const int akoff = (lane >> 4) * 16;                      // A k-half
    const int bq = lane >> 3, br = lane & 7;
    const int boffs = ((bq >> 1) * 8 + br) * ROW_BYTES + (bq & 1) * 16;

    while (cur < NCELLS) {
        const int am0 = (cur >> 6) * BLK_M;
        const int n0  = (cur & 63) * BLK_N;

        for (int s = 0; s < KST; s++) {
            CP_WAIT1();
            __syncthreads();
            if (s == 10 && tid == 0) sCell[1] = atomicAdd(&g_work, 1);
            if (s < KST - 2) {
                stage_cp(sbase, (rs + 2) % 3, am0, n0, (s + 2) * 32, tid);
            } else {
                const int nx = sCell[1];   // written s==10, barriers since
                if (nx < NCELLS)
                    stage_cp(sbase, (rs + 2) % 3, (nx >> 6) * BLK_M,
                             (nx & 63) * BLK_N, (s - (KST - 2)) * 32, tid);
            }
            CP_COMMIT();

            const uint32_t buf = sbase + rs * STAGE_BYTES;

#pragma unroll
            for (int ks = 0; ks < 2; ks++) {
                const uint32_t kso = ks * 32;
                // B fragments (2 x ldmatrix.x4)
                uint32_t bF[4][2];
                {
                    const uint32_t bb = buf + A_TILE_BYTES
                                      + (warp_n * 32) * ROW_BYTES + boffs + kso;
                    uint32_t r0[4], r1[4];
                    ldmatrix_x4(r0, bb);
                    ldmatrix_x4(r1, bb + 16 * ROW_BYTES);
                    bF[0][0] = r0[0]; bF[0][1] = r0[1];
                    bF[1][0] = r0[2]; bF[1][1] = r0[3];
                    bF[2][0] = r1[0]; bF[2][1] = r1[1];
                    bF[3][0] = r1[2]; bF[3][1] = r1[3];
                }
                // A fragments (2 x ldmatrix.x4)
                uint32_t aF[2][4];
#pragma unroll
                for (int mi = 0; mi < 2; mi++)
                    ldmatrix_x4(aF[mi], buf
                        + (warp_m * 32 + mi * 16 + arow8) * ROW_BYTES
                        + akoff + kso);
                // 8 independent MMAs
#pragma unroll
                for (int mi = 0; mi < 2; mi++)
#pragma unroll
                    for (int ni = 0; ni < 4; ni++)
                        mma_f16(acc[mi][ni], aF[mi], bF[ni]);
            }

            // epilogue at end of cell: s = cnorm - 2*dot (bias deferred)
            if (s == KST - 1) {
#pragma unroll
                for (int mi = 0; mi < 2; mi++) {
#pragma unroll
                    for (int h = 0; h < 2; h++) {
                        const int r = warp_m * 32 + mi * 16 + (lane >> 2) + h * 8;
                        __half* srow = &g_scores[(size_t)(am0 + r) * KCB];
#pragma unroll
                        for (int ni = 0; ni < 4; ni++) {
                            const int n = n0 + warp_n * 32 + ni * 8 + (lane & 3) * 2;
                            float2 cn = *reinterpret_cast<const float2*>(g_cnorm + n);
                            float s0 = cn.x - 2.0f * acc[mi][ni][h * 2 + 0];
                            float s1 = cn.y - 2.0f * acc[mi][ni][h * 2 + 1];
                            *reinterpret_cast<__half2*>(srow + n) =
                                __floats2half2_rn(s0, s1);
                        }
                    }
                }
#pragma unroll
                for (int mi = 0; mi < 2; mi++)
#pragma unroll
                    for (int ni = 0; ni < 4; ni++)
#pragma unroll
                        for (int e = 0; e < 4; e++) acc[mi][ni][e] = 0.f;
            }
            rs = (rs == 2) ? 0 : rs + 1;
        }
        cur = sCell[1];
    }
}

// ---------------------------------------------------------------------------
// Kernel 4: per-row filter + exact fp32 rescore (incl. sigmoid bias) -> g_idx
// ---------------------------------------------------------------------------
__global__ __launch_bounds__(128) void filter_kernel(
    const float* __restrict__ zr, const float* __restrict__ zi,
    const float* __restrict__ cb, const float* __restrict__ adj)
{
    __shared__ float zsh[D2];
    __shared__ int   cand[1024];
    __shared__ int   ccount;
    __shared__ float red[4];
    __shared__ float rowmin_sh;

    const int row  = blockIdx.x;
    const int tid  = threadIdx.x;
    const int lane = tid & 31;
    const int wrp  = tid >> 5;

    // load z row (f32 exact)
    {
        int j = tid * 4;
        float4 v = (j < DHALF)
            ? *reinterpret_cast<const float4*>(zr + (size_t)row * DHALF + j)
            : *reinterpret_cast<const float4*>(zi + (size_t)row * DHALF + (j - DHALF));
        *reinterpret_cast<float4*>(&zsh[j]) = v;
    }
    if (tid == 0) ccount = 0;

    // load this thread's 32 scores (64B contiguous)
    const __half* srow = &g_scores[(size_t)row * KCB];
    uint4 raw[4];
#pragma unroll
    for (int i = 0; i < 4; i++)
        raw[i] = *reinterpret_cast<const uint4*>(srow + tid * 32 + i * 8);
    const __half2* h2 = reinterpret_cast<const __half2*>(raw);

    float smin = 1e30f;
#pragma unroll
    for (int i = 0; i < 16; i++) {
        float2 f = __half22float2(h2[i]);
        smin = fminf(smin, fminf(f.x, f.y));
    }
#pragma unroll
    for (int o = 16; o; o >>= 1)
        smin = fminf(smin, __shfl_xor_sync(0xffffffffu, smin, o));
    if (lane == 0) red[wrp] = smin;
    __syncthreads();
    if (tid == 0)
        rowmin_sh = fminf(fminf(red[0], red[1]), fminf(red[2], red[3]));
    __syncthreads();

    const float thr = rowmin_sh + MARGIN;
#pragma unroll
    for (int i = 0; i < 16; i++) {
        float2 f = __half22float2(h2[i]);
        if (f.x <= thr) { int p = atomicAdd(&ccount, 1); if (p < 1024) cand[p] = tid * 32 + i * 2; }
        if (f.y <= thr) { int p = atomicAdd(&ccount, 1); if (p < 1024) cand[p] = tid * 32 + i * 2 + 1; }
    }
    __syncthreads();

    const int cnt = (ccount < 1024) ? ccount : 1024;
    unsigned long long best = ~0ULL;
    const int myprev = g_prev[row];

    for (int i = 0; i < cnt; i++) {
        const int n = cand[i];
        float4 cv = reinterpret_cast<const float4*>(cb + (size_t)n * D2)[tid];
        const int j = tid * 4;
        float d = zsh[j] * cv.x + zsh[j + 1] * cv.y
                + zsh[j + 2] * cv.z + zsh[j + 3] * cv.w;
#pragma unroll
        for (int o = 16; o; o >>= 1) d += __shfl_xor_sync(0xffffffffu, d, o);
        if (lane == 0) red[wrp] = d;
        __syncthreads();
        if (tid == 0) {
            float dot = red[0] + red[1] + red[2] + red[3];
            float s = g_cnorm[n] - 2.0f * dot
                    - sig08(adj[(size_t)myprev * KCB + n]);
            unsigned long long k = score_key(s, n);
            best = (k < best) ? k : best;
        }
        __syncthreads();
    }
    if (tid == 0) g_idx[row] = (int)(best & 0xffffffffu);
}

// ---------------------------------------------------------------------------
// Kernel 5: gather z_q = codebook[idx], write outputs, per-row squared error
// ---------------------------------------------------------------------------
__global__ void gather_kernel(const float* __restrict__ zr,
                              const float* __restrict__ zi,
                              const float* __restrict__ cb,
                              float* __restrict__ out)
{
    __shared__ float sw[4];
    const int row = blockIdx.x;
    const int tid = threadIdx.x;
    const int idx = g_idx[row];
    const int j   = tid * 4;

    float4 c = *reinterpret_cast<const float4*>(cb + (size_t)idx * D2 + j);
    float4 z;
    float* o;
    if (j < DHALF) {
        z = *reinterpret_cast<const float4*>(zr + (size_t)row * DHALF + j);
        o = out + OUT_REAL_OFF + (size_t)row * DHALF + j;
    } else {
        z = *reinterpret_cast<const float4*>(zi + (size_t)row * DHALF + (j - DHALF));
        o = out + OUT_IMAG_OFF + (size_t)row * DHALF + (j - DHALF);
    }
    *reinterpret_cast<float4*>(o) = c;

    float dx = c.x - z.x, dy = c.y - z.y, dz = c.z - z.z, dw = c.w - z.w;
    float s = dx * dx + dy * dy + dz * dz + dw * dw;
#pragma unroll
    for (int of = 16; of; of >>= 1) s += __shfl_xor_sync(0xffffffffu, s, of);
    if ((tid & 31) == 0) sw[tid >> 5] = s;
    __syncthreads();
    if (tid == 0) {
        g_rowsum[row] = sw[0] + sw[1] + sw[2] + sw[3];
        out[OUT_IDX_OFF + row] = (float)idx;
    }
}

// ---------------------------------------------------------------------------
// Kernel 6: deterministic final loss reduction
// ---------------------------------------------------------------------------
__global__ void loss_kernel(float* __restrict__ out) {
    __shared__ float sm[1024];
    const int tid = threadIdx.x;
    float s = 0.f;
#pragma unroll 1
    for (int k = 0; k < 32; k++) s += g_rowsum[tid + 1024 * k];
    sm[tid] = s;
    __syncthreads();
    for (int off = 512; off; off >>= 1) {
        if (tid < off) sm[tid] += sm[tid + off];
        __syncthreads();
    }
    if (tid == 0) out[OUT_LOSS_OFF] = sm[0] * (1.01f / 16777216.0f);
}

// ---------------------------------------------------------------------------
extern "C" void kernel_launch(void* const* d_in, const int* in_sizes, int n_in,
                              void* d_out, int out_size) {
    const float* zr   = (const float*)d_in[0];
    const float* zi   = (const float*)d_in[1];
    const void*  prev = d_in[2];
    const float* cb   = (const float*)d_in[3];
    const float* adj  = (const float*)d_in[4];
    float* out = (float*)d_out;

    cudaFuncSetAttribute(vq_screen_kernel,
                         cudaFuncAttributeMaxDynamicSharedMemorySize, SMEM_TOTAL);

    int dev = 0, nsm = 148;
    cudaGetDevice(&dev);
    cudaDeviceGetAttribute(&nsm, cudaDevAttrMultiProcessorCount, dev);
    int grid = 4 * nsm;
    if (grid > NCELLS) grid = NCELLS;

    prev_kernel<<<(M_TOTAL + 255) / 256, 256>>>(prev);
    cnorm_kernel<<<KCB / 8, 256>>>(cb);
    split_kernel<<<(M_TOTAL * D2 / 4) / 256 + (KCB * D2 / 4) / 256, 256>>>(zr, zi, cb);
    vq_screen_kernel<<<grid, 256, SMEM_TOTAL>>>();   // launch #4 -> ncu
    filter_kernel<<<M_TOTAL, 128>>>(zr, zi, cb, adj);
    gather_kernel<<<M_TOTAL, 128>>>(zr, zi, cb, out);
    loss_kernel<<<1, 1024>>>(out);
}